// round 1
// baseline (speedup 1.0000x reference)
#include <cuda_runtime.h>

#define L1N 512
#define L2N 512
#define BB  2
#define D1N 256
#define D2N 256
#define BNN 256
#define NEGC (-1.0e12f)

// ---------------- device scratch (no allocations allowed) ----------------
__device__ float g_p1[BB*L1N*BNN];   // [b][l][k]  ctx1 @ Wh[:D1]
__device__ float g_p2[BB*L2N*BNN];   // [b][m][k]  ctx2 @ Wh[D1:] + bh
__device__ float g_q1[BB*L1N*BNN];   // [b][l][k]  ctx1 @ W21[:D1]
__device__ float g_q2[BB*L2N*BNN];   // [b][m][k]  ctx2 @ W12[:D2]
__device__ float g_aff[BB*L1N*L2N];  // [b][l][m]
__device__ float g_d12[BB*L1N*L2N];  // softmax over m
__device__ float g_d21[BB*L1N*L2N];  // softmax over l
__device__ float g_c12[BB*L2N*D1N];  // [b][m][d]
__device__ float g_c21[BB*L1N*D2N];  // [b][l][d]
__device__ float g_cmax[BB*L2N];
__device__ float g_csum[BB*L2N];

__device__ __forceinline__ float tanh_fast(float x){
    float y; asm("tanh.approx.f32 %0, %1;" : "=f"(y) : "f"(x)); return y;
}

// =====================================================================
// Projections: 4 GEMMs (512x256 @ 256x256 per b), merged in one launch.
// mode 0: p1 = ctx1 @ Wh[:D1]
// mode 1: p2 = ctx2 @ Wh[D1:] + bh
// mode 2: q2 = ctx2 @ W12[:D2]
// mode 3: q1 = ctx1 @ W21[:D1]
// grid (BNN/64, 512/64, 4*BB), 256 threads
// =====================================================================
__global__ __launch_bounds__(256) void proj4_kernel(
    const float* __restrict__ ctx1, const float* __restrict__ ctx2,
    const float* __restrict__ Wh,  const float* __restrict__ bh,
    const float* __restrict__ W12, const float* __restrict__ W21)
{
    const int mode = blockIdx.z >> 1;
    const int b    = blockIdx.z & 1;
    const float* X; const float* W; const float* bias; float* P;
    if (mode == 0)      { X = ctx1; W = Wh;             bias = nullptr; P = g_p1; }
    else if (mode == 1) { X = ctx2; W = Wh + D1N*BNN;   bias = bh;      P = g_p2; }
    else if (mode == 2) { X = ctx2; W = W12;            bias = nullptr; P = g_q2; }
    else                { X = ctx1; W = W21;            bias = nullptr; P = g_q1; }

    const int i0 = blockIdx.y * 64;
    const int j0 = blockIdx.x * 64;
    const int tid = threadIdx.x;
    __shared__ float As[16][68];   // As[d][i], padded (bank + 16B-align friendly)
    __shared__ float Bs[16][64];   // Bs[d][j]
    float acc[4][4] = {};
    const int ai = tid >> 2, ad = (tid & 3) << 2;
    const int bk = tid >> 4, bj = (tid & 15) << 2;
    const int ti = (tid >> 4) << 2, tj = (tid & 15) << 2;

    for (int d0 = 0; d0 < D1N; d0 += 16) {
        float4 av = *(const float4*)&X[((size_t)(i0+ai)*BB + b)*D1N + d0 + ad];
        As[ad+0][ai]=av.x; As[ad+1][ai]=av.y; As[ad+2][ai]=av.z; As[ad+3][ai]=av.w;
        *(float4*)&Bs[bk][bj] = *(const float4*)&W[(size_t)(d0+bk)*BNN + j0 + bj];
        __syncthreads();
        #pragma unroll
        for (int k = 0; k < 16; ++k) {
            const float4 a = *(const float4*)&As[k][ti];
            const float4 w = *(const float4*)&Bs[k][tj];
            const float ar[4]={a.x,a.y,a.z,a.w}, br[4]={w.x,w.y,w.z,w.w};
            #pragma unroll
            for (int r=0;r<4;r++)
                #pragma unroll
                for (int c=0;c<4;c++)
                    acc[r][c] = fmaf(ar[r], br[c], acc[r][c]);
        }
        __syncthreads();
    }
    float4 bb = bias ? *(const float4*)&bias[j0+tj] : make_float4(0.f,0.f,0.f,0.f);
    #pragma unroll
    for (int r=0;r<4;r++){
        float4 o = make_float4(acc[r][0]+bb.x, acc[r][1]+bb.y,
                               acc[r][2]+bb.z, acc[r][3]+bb.w);
        *(float4*)&P[((size_t)(b*L1N)+(i0+ti+r))*BNN + j0 + tj] = o;
    }
}

// =====================================================================
// Affinity: aff[b,l,m] = sum_k wo[k]*tanh(p1[b,l,k]+p2[b,m,k]) + mask terms
// grid (L2/64, L1/64, B), 256 threads, 4x4 per thread. MUFU-bound by design.
// =====================================================================
__global__ __launch_bounds__(256) void affinity_kernel(
    const float* __restrict__ m1, const float* __restrict__ m2,
    const float* __restrict__ wo)
{
    const int b  = blockIdx.z;
    const int l0 = blockIdx.y * 64;
    const int m0 = blockIdx.x * 64;
    const int tid = threadIdx.x;
    __shared__ float P1s[16][68];
    __shared__ float P2s[16][68];
    __shared__ float wos[BNN];
    wos[tid] = wo[tid];
    float acc[4][4] = {};
    const int ai = tid >> 2, ad = (tid & 3) << 2;
    const int ti = (tid >> 4) << 2, tm = (tid & 15) << 2;

    for (int k0 = 0; k0 < BNN; k0 += 16) {
        float4 a = *(const float4*)&g_p1[((size_t)(b*L1N)+(l0+ai))*BNN + k0 + ad];
        P1s[ad+0][ai]=a.x; P1s[ad+1][ai]=a.y; P1s[ad+2][ai]=a.z; P1s[ad+3][ai]=a.w;
        float4 c = *(const float4*)&g_p2[((size_t)(b*L2N)+(m0+ai))*BNN + k0 + ad];
        P2s[ad+0][ai]=c.x; P2s[ad+1][ai]=c.y; P2s[ad+2][ai]=c.z; P2s[ad+3][ai]=c.w;
        __syncthreads();
        #pragma unroll
        for (int kk = 0; kk < 16; ++kk) {
            const float w = wos[k0+kk];
            const float4 av = *(const float4*)&P1s[kk][ti];
            const float4 cv = *(const float4*)&P2s[kk][tm];
            const float ar[4]={av.x,av.y,av.z,av.w}, cr[4]={cv.x,cv.y,cv.z,cv.w};
            #pragma unroll
            for (int r=0;r<4;r++)
                #pragma unroll
                for (int c=0;c<4;c++)
                    acc[r][c] = fmaf(w, tanh_fast(ar[r]+cr[c]), acc[r][c]);
        }
        __syncthreads();
    }
    float mrow[4], mcol[4];
    #pragma unroll
    for (int r=0;r<4;r++) mrow[r] = (1.0f - m1[(l0+ti+r)*BB + b]) * NEGC;
    #pragma unroll
    for (int c=0;c<4;c++) mcol[c] = (1.0f - m2[(m0+tm+c)*BB + b]) * NEGC;
    #pragma unroll
    for (int r=0;r<4;r++){
        float v0 = acc[r][0] + mrow[r]; v0 += mcol[0];
        float v1 = acc[r][1] + mrow[r]; v1 += mcol[1];
        float v2 = acc[r][2] + mrow[r]; v2 += mcol[2];
        float v3 = acc[r][3] + mrow[r]; v3 += mcol[3];
        *(float4*)&g_aff[((size_t)(b*L1N)+(l0+ti+r))*L2N + m0 + tm]
            = make_float4(v0,v1,v2,v3);
    }
}

// =====================================================================
// Row softmax (axis=2, over m): one block per (b,l) row of 512.
// =====================================================================
__global__ __launch_bounds__(128) void softmax_rows_kernel()
{
    const int row = blockIdx.x;            // b*L1N + l
    const float4 v = ((const float4*)&g_aff[(size_t)row*L2N])[threadIdx.x];
    float mx = fmaxf(fmaxf(v.x,v.y), fmaxf(v.z,v.w));
    #pragma unroll
    for (int o=16;o;o>>=1) mx = fmaxf(mx, __shfl_xor_sync(0xffffffffu, mx, o));
    __shared__ float redm[4], reds[4];
    const int wid = threadIdx.x >> 5, lane = threadIdx.x & 31;
    if (!lane) redm[wid] = mx;
    __syncthreads();
    mx = fmaxf(fmaxf(redm[0],redm[1]), fmaxf(redm[2],redm[3]));
    float e0=__expf(v.x-mx), e1=__expf(v.y-mx), e2=__expf(v.z-mx), e3=__expf(v.w-mx);
    float s = (e0+e1)+(e2+e3);
    #pragma unroll
    for (int o=16;o;o>>=1) s += __shfl_xor_sync(0xffffffffu, s, o);
    if (!lane) reds[wid] = s;
    __syncthreads();
    s = (reds[0]+reds[1])+(reds[2]+reds[3]);
    const float inv = 1.0f / s;
    ((float4*)&g_d12[(size_t)row*L2N])[threadIdx.x]
        = make_float4(e0*inv, e1*inv, e2*inv, e3*inv);
}

// =====================================================================
// Column softmax (axis=1, over l): stats pass + write pass.
// =====================================================================
__global__ __launch_bounds__(128) void colstats_kernel()
{
    const int b = blockIdx.y;
    const int m = blockIdx.x*128 + threadIdx.x;
    const float* a = g_aff + (size_t)b*L1N*L2N + m;
    float m0=-3.4e38f,m1v=-3.4e38f,m2v=-3.4e38f,m3=-3.4e38f;
    for (int l=0;l<L1N;l+=4){
        m0=fmaxf(m0,a[(size_t)(l+0)*L2N]); m1v=fmaxf(m1v,a[(size_t)(l+1)*L2N]);
        m2v=fmaxf(m2v,a[(size_t)(l+2)*L2N]); m3=fmaxf(m3,a[(size_t)(l+3)*L2N]);
    }
    const float mx = fmaxf(fmaxf(m0,m1v), fmaxf(m2v,m3));
    float s0=0.f,s1=0.f,s2=0.f,s3=0.f;
    for (int l=0;l<L1N;l+=4){
        s0+=__expf(a[(size_t)(l+0)*L2N]-mx); s1+=__expf(a[(size_t)(l+1)*L2N]-mx);
        s2+=__expf(a[(size_t)(l+2)*L2N]-mx); s3+=__expf(a[(size_t)(l+3)*L2N]-mx);
    }
    g_cmax[b*L2N+m]=mx;
    g_csum[b*L2N+m]=(s0+s1)+(s2+s3);
}

__global__ __launch_bounds__(128) void colwrite_kernel()
{
    const int b = blockIdx.z;
    const int m = blockIdx.x*128 + threadIdx.x;
    const int l0 = blockIdx.y*32;
    const float mx  = g_cmax[b*L2N+m];
    const float inv = 1.0f / g_csum[b*L2N+m];
    #pragma unroll 8
    for (int l=l0; l<l0+32; ++l){
        const size_t idx = ((size_t)(b*L1N)+l)*L2N + m;
        g_d21[idx] = __expf(g_aff[idx]-mx)*inv;
    }
}

// =====================================================================
// Context GEMMs (merged):
//  which=0: c12[b,m,d] = sum_l d12[b,l,m] * ctx1[l,b,d]   (A col-major)
//  which=1: c21[b,l,d] = sum_m d21[b,l,m] * ctx2[m,b,d]   (A row-major)
// grid (256/64, 512/64, 2*BB), 256 threads
// =====================================================================
__global__ __launch_bounds__(256) void context_kernel(
    const float* __restrict__ ctx1, const float* __restrict__ ctx2)
{
    const int which = blockIdx.z >> 1;
    const int b     = blockIdx.z & 1;
    const float* Asrc = which ? g_d21 : g_d12;
    const float* Bsrc = which ? ctx2  : ctx1;
    float*       Cdst = which ? g_c21 : g_c12;
    const int i0 = blockIdx.y * 64;
    const int j0 = blockIdx.x * 64;
    const int tid = threadIdx.x;
    __shared__ float As[16][68];
    __shared__ float Bs[16][64];
    float acc[4][4] = {};
    const int ai = tid >> 2, ad = (tid & 3) << 2;
    const int ak = tid >> 4, am = (tid & 15) << 2;
    const int bk = tid >> 4, bj = (tid & 15) << 2;
    const int ti = (tid >> 4) << 2, tj = (tid & 15) << 2;

    for (int k0 = 0; k0 < L1N; k0 += 16) {
        if (which == 0) {
            *(float4*)&As[ak][am]
                = *(const float4*)&Asrc[((size_t)(b*L1N)+(k0+ak))*L2N + i0 + am];
        } else {
            float4 av = *(const float4*)&Asrc[((size_t)(b*L1N)+(i0+ai))*L2N + k0 + ad];
            As[ad+0][ai]=av.x; As[ad+1][ai]=av.y; As[ad+2][ai]=av.z; As[ad+3][ai]=av.w;
        }
        *(float4*)&Bs[bk][bj]
            = *(const float4*)&Bsrc[((size_t)(k0+bk)*BB + b)*D1N + j0 + bj];
        __syncthreads();
        #pragma unroll
        for (int k = 0; k < 16; ++k) {
            const float4 a = *(const float4*)&As[k][ti];
            const float4 w = *(const float4*)&Bs[k][tj];
            const float ar[4]={a.x,a.y,a.z,a.w}, br[4]={w.x,w.y,w.z,w.w};
            #pragma unroll
            for (int r=0;r<4;r++)
                #pragma unroll
                for (int c=0;c<4;c++)
                    acc[r][c] = fmaf(ar[r], br[c], acc[r][c]);
        }
        __syncthreads();
    }
    #pragma unroll
    for (int r=0;r<4;r++)
        *(float4*)&Cdst[((size_t)(b*L1N)+(i0+ti+r))*D1N + j0 + tj]
            = make_float4(acc[r][0],acc[r][1],acc[r][2],acc[r][3]);
}

// =====================================================================
// Output GEMMs (merged) + epilogue tanh + scatter:
//  which=0: seq_2_to_1[l,b,:] = tanh(q1 + c21 @ W21[D1:] + b21) -> out[0..]
//  which=1: seq_1_to_2[m,b,:] = tanh(q2 + c12 @ W12[D2:] + b12) -> out[L1*B*BN..]
// grid (256/64, 1024/64, 2), 256 threads
// =====================================================================
__global__ __launch_bounds__(256) void out_kernel(
    const float* __restrict__ W12, const float* __restrict__ b12,
    const float* __restrict__ W21, const float* __restrict__ b21,
    float* __restrict__ out)
{
    const int which = blockIdx.z;
    const float* A    = which ? g_c12 : g_c21;
    const float* Bm   = which ? (W12 + (size_t)D2N*BNN) : (W21 + (size_t)D1N*BNN);
    const float* bias = which ? b12 : b21;
    const float* Q    = which ? g_q2 : g_q1;
    float* O          = out + (which ? (size_t)L1N*BB*BNN : 0);
    const int i0 = blockIdx.y * 64;
    const int j0 = blockIdx.x * 64;
    const int tid = threadIdx.x;
    __shared__ float As[16][68];
    __shared__ float Bs[16][64];
    float acc[4][4] = {};
    const int ai = tid >> 2, ad = (tid & 3) << 2;
    const int bk = tid >> 4, bj = (tid & 15) << 2;
    const int ti = (tid >> 4) << 2, tj = (tid & 15) << 2;

    for (int k0 = 0; k0 < D1N; k0 += 16) {
        float4 av = *(const float4*)&A[(size_t)(i0+ai)*D1N + k0 + ad];
        As[ad+0][ai]=av.x; As[ad+1][ai]=av.y; As[ad+2][ai]=av.z; As[ad+3][ai]=av.w;
        *(float4*)&Bs[bk][bj] = *(const float4*)&Bm[(size_t)(k0+bk)*BNN + j0 + bj];
        __syncthreads();
        #pragma unroll
        for (int k = 0; k < 16; ++k) {
            const float4 a = *(const float4*)&As[k][ti];
            const float4 w = *(const float4*)&Bs[k][tj];
            const float ar[4]={a.x,a.y,a.z,a.w}, br[4]={w.x,w.y,w.z,w.w};
            #pragma unroll
            for (int r=0;r<4;r++)
                #pragma unroll
                for (int c=0;c<4;c++)
                    acc[r][c] = fmaf(ar[r], br[c], acc[r][c]);
        }
        __syncthreads();
    }
    const float4 bb = *(const float4*)&bias[j0+tj];
    #pragma unroll
    for (int r=0;r<4;r++){
        const int row = i0+ti+r;              // row = b*512 + seqpos
        const int b = row >> 9, sp = row & 511;
        const float4 q = *(const float4*)&Q[(size_t)row*BNN + j0 + tj];
        float4 o;
        o.x = tanhf(acc[r][0]+q.x+bb.x);
        o.y = tanhf(acc[r][1]+q.y+bb.y);
        o.z = tanhf(acc[r][2]+q.z+bb.z);
        o.w = tanhf(acc[r][3]+q.w+bb.w);
        *(float4*)&O[((size_t)(sp*BB)+b)*BNN + j0 + tj] = o;
    }
}

// =====================================================================
extern "C" void kernel_launch(void* const* d_in, const int* in_sizes, int n_in,
                              void* d_out, int out_size)
{
    (void)in_sizes; (void)n_in; (void)out_size;
    const float* ctx1 = (const float*)d_in[0];
    const float* ctx2 = (const float*)d_in[1];
    const float* m1   = (const float*)d_in[2];
    const float* m2   = (const float*)d_in[3];
    const float* Wh   = (const float*)d_in[4];
    const float* bh   = (const float*)d_in[5];
    const float* wo   = (const float*)d_in[6];
    const float* W12  = (const float*)d_in[7];
    const float* b12  = (const float*)d_in[8];
    const float* W21  = (const float*)d_in[9];
    const float* b21  = (const float*)d_in[10];
    float* out = (float*)d_out;

    proj4_kernel     <<<dim3(BNN/64, L1N/64, 4*BB), 256>>>(ctx1, ctx2, Wh, bh, W12, W21);
    affinity_kernel  <<<dim3(L2N/64, L1N/64, BB),   256>>>(m1, m2, wo);
    softmax_rows_kernel<<<BB*L1N, 128>>>();
    colstats_kernel  <<<dim3(L2N/128, BB), 128>>>();
    colwrite_kernel  <<<dim3(L2N/128, L1N/32, BB), 128>>>();
    context_kernel   <<<dim3(D1N/64, L2N/64, 2*BB), 256>>>(ctx1, ctx2);
    out_kernel       <<<dim3(BNN/64, (BB*L1N)/64, 2), 256>>>(W12, b12, W21, b21, out);
}

// round 2
// speedup vs baseline: 1.2342x; 1.2342x over previous
#include <cuda_runtime.h>

#define L1N 512
#define L2N 512
#define BB  2
#define D1N 256
#define D2N 256
#define BNN 256
#define NEGC (-1.0e12f)

// ---------------- device scratch (no allocations allowed) ----------------
__device__ float g_p1[BB*L1N*BNN];    // [b][l][k]  ctx1 @ Wh[:D1]
__device__ float g_p2[BB*L2N*BNN];    // [b][m][k]  ctx2 @ Wh[D1:] + bh
__device__ float g_q1[BB*L1N*BNN];    // [b][l][k]  ctx1 @ W21[:D1]
__device__ float g_q2[BB*L2N*BNN];    // [b][m][k]  ctx2 @ W12[:D2]
__device__ float g_aff [BB*L1N*L2N];  // [b][l][m]
__device__ float g_afft[BB*L2N*L1N];  // [b][m][l]  (transposed copy)
__device__ float g_d12 [BB*L1N*L2N];  // softmax over m       [b][l][m]
__device__ float g_d21t[BB*L2N*L1N];  // softmax over l, T'd  [b][m][l]
__device__ float g_c12[BB*L2N*D1N];   // [b][m][d]
__device__ float g_c21[BB*L1N*D2N];   // [b][l][d]

__device__ __forceinline__ float tanh_fast(float x){
    float y; asm("tanh.approx.f32 %0, %1;" : "=f"(y) : "f"(x)); return y;
}

// =====================================================================
// Projections: 4 GEMMs (512x256 @ 256x256 per b), merged in one launch.
// grid (BNN/64, 512/64, 4*BB), 256 threads
// =====================================================================
__global__ __launch_bounds__(256) void proj4_kernel(
    const float* __restrict__ ctx1, const float* __restrict__ ctx2,
    const float* __restrict__ Wh,  const float* __restrict__ bh,
    const float* __restrict__ W12, const float* __restrict__ W21)
{
    const int mode = blockIdx.z >> 1;
    const int b    = blockIdx.z & 1;
    const float* X; const float* W; const float* bias; float* P;
    if (mode == 0)      { X = ctx1; W = Wh;             bias = nullptr; P = g_p1; }
    else if (mode == 1) { X = ctx2; W = Wh + D1N*BNN;   bias = bh;      P = g_p2; }
    else if (mode == 2) { X = ctx2; W = W12;            bias = nullptr; P = g_q2; }
    else                { X = ctx1; W = W21;            bias = nullptr; P = g_q1; }

    const int i0 = blockIdx.y * 64;
    const int j0 = blockIdx.x * 64;
    const int tid = threadIdx.x;
    __shared__ float As[16][68];
    __shared__ float Bs[16][64];
    float acc[4][4] = {};
    const int ai = tid >> 2, ad = (tid & 3) << 2;
    const int bk = tid >> 4, bj = (tid & 15) << 2;
    const int ti = (tid >> 4) << 2, tj = (tid & 15) << 2;

    for (int d0 = 0; d0 < D1N; d0 += 16) {
        float4 av = *(const float4*)&X[((size_t)(i0+ai)*BB + b)*D1N + d0 + ad];
        As[ad+0][ai]=av.x; As[ad+1][ai]=av.y; As[ad+2][ai]=av.z; As[ad+3][ai]=av.w;
        *(float4*)&Bs[bk][bj] = *(const float4*)&W[(size_t)(d0+bk)*BNN + j0 + bj];
        __syncthreads();
        #pragma unroll
        for (int k = 0; k < 16; ++k) {
            const float4 a = *(const float4*)&As[k][ti];
            const float4 w = *(const float4*)&Bs[k][tj];
            const float ar[4]={a.x,a.y,a.z,a.w}, br[4]={w.x,w.y,w.z,w.w};
            #pragma unroll
            for (int r=0;r<4;r++)
                #pragma unroll
                for (int c=0;c<4;c++)
                    acc[r][c] = fmaf(ar[r], br[c], acc[r][c]);
        }
        __syncthreads();
    }
    float4 bb = bias ? *(const float4*)&bias[j0+tj] : make_float4(0.f,0.f,0.f,0.f);
    #pragma unroll
    for (int r=0;r<4;r++){
        float4 o = make_float4(acc[r][0]+bb.x, acc[r][1]+bb.y,
                               acc[r][2]+bb.z, acc[r][3]+bb.w);
        *(float4*)&P[((size_t)(b*L1N)+(i0+ti+r))*BNN + j0 + tj] = o;
    }
}

// =====================================================================
// Affinity: aff[b,l,m] = sum_k wo[k]*tanh(p1[b,l,k]+p2[b,m,k]) + mask terms
// Writes BOTH row-major g_aff[l][m] and transposed g_afft[m][l] so both
// softmaxes become row softmaxes (coalesced).
// grid (L2/64, L1/64, B), 256 threads, 4x4 per thread. MUFU-bound.
// =====================================================================
__global__ __launch_bounds__(256) void affinity_kernel(
    const float* __restrict__ m1, const float* __restrict__ m2,
    const float* __restrict__ wo)
{
    const int b  = blockIdx.z;
    const int l0 = blockIdx.y * 64;
    const int m0 = blockIdx.x * 64;
    const int tid = threadIdx.x;
    __shared__ float P1s[16][68];
    __shared__ float P2s[16][68];
    __shared__ float wos[BNN];
    wos[tid] = wo[tid];
    float acc[4][4] = {};
    const int ai = tid >> 2, ad = (tid & 3) << 2;
    const int ti = (tid >> 4) << 2, tm = (tid & 15) << 2;

    for (int k0 = 0; k0 < BNN; k0 += 16) {
        float4 a = *(const float4*)&g_p1[((size_t)(b*L1N)+(l0+ai))*BNN + k0 + ad];
        P1s[ad+0][ai]=a.x; P1s[ad+1][ai]=a.y; P1s[ad+2][ai]=a.z; P1s[ad+3][ai]=a.w;
        float4 c = *(const float4*)&g_p2[((size_t)(b*L2N)+(m0+ai))*BNN + k0 + ad];
        P2s[ad+0][ai]=c.x; P2s[ad+1][ai]=c.y; P2s[ad+2][ai]=c.z; P2s[ad+3][ai]=c.w;
        __syncthreads();
        #pragma unroll
        for (int kk = 0; kk < 16; ++kk) {
            const float w = wos[k0+kk];
            const float4 av = *(const float4*)&P1s[kk][ti];
            const float4 cv = *(const float4*)&P2s[kk][tm];
            const float ar[4]={av.x,av.y,av.z,av.w}, cr[4]={cv.x,cv.y,cv.z,cv.w};
            #pragma unroll
            for (int r=0;r<4;r++)
                #pragma unroll
                for (int c=0;c<4;c++)
                    acc[r][c] = fmaf(w, tanh_fast(ar[r]+cr[c]), acc[r][c]);
        }
        __syncthreads();
    }
    float mrow[4], mcol[4];
    #pragma unroll
    for (int r=0;r<4;r++) mrow[r] = (1.0f - m1[(l0+ti+r)*BB + b]) * NEGC;
    #pragma unroll
    for (int c=0;c<4;c++) mcol[c] = (1.0f - m2[(m0+tm+c)*BB + b]) * NEGC;
    #pragma unroll
    for (int r=0;r<4;r++)
        #pragma unroll
        for (int c=0;c<4;c++)
            acc[r][c] += mrow[r] + mcol[c];
    // row-major store
    #pragma unroll
    for (int r=0;r<4;r++)
        *(float4*)&g_aff[((size_t)(b*L1N)+(l0+ti+r))*L2N + m0 + tm]
            = make_float4(acc[r][0],acc[r][1],acc[r][2],acc[r][3]);
    // transposed store: 4 consecutive l per float4
    #pragma unroll
    for (int c=0;c<4;c++)
        *(float4*)&g_afft[((size_t)(b*L2N)+(m0+tm+c))*L1N + l0 + ti]
            = make_float4(acc[0][c],acc[1][c],acc[2][c],acc[3][c]);
}

// =====================================================================
// Dual row softmax: grid (B*512, 2); y=0: g_aff->g_d12, y=1: g_afft->g_d21t
// 128 threads, 4 elems each, fully coalesced.
// =====================================================================
__global__ __launch_bounds__(128) void softmax_dual_kernel()
{
    const int row = blockIdx.x;
    const float* src = blockIdx.y ? g_afft : g_aff;
    float*       dst = blockIdx.y ? g_d21t : g_d12;
    const float4 v = ((const float4*)&src[(size_t)row*512])[threadIdx.x];
    float mx = fmaxf(fmaxf(v.x,v.y), fmaxf(v.z,v.w));
    #pragma unroll
    for (int o=16;o;o>>=1) mx = fmaxf(mx, __shfl_xor_sync(0xffffffffu, mx, o));
    __shared__ float redm[4], reds[4];
    const int wid = threadIdx.x >> 5, lane = threadIdx.x & 31;
    if (!lane) redm[wid] = mx;
    __syncthreads();
    mx = fmaxf(fmaxf(redm[0],redm[1]), fmaxf(redm[2],redm[3]));
    float e0=__expf(v.x-mx), e1=__expf(v.y-mx), e2=__expf(v.z-mx), e3=__expf(v.w-mx);
    float s = (e0+e1)+(e2+e3);
    #pragma unroll
    for (int o=16;o;o>>=1) s += __shfl_xor_sync(0xffffffffu, s, o);
    if (!lane) reds[wid] = s;
    __syncthreads();
    s = (reds[0]+reds[1])+(reds[2]+reds[3]);
    const float inv = 1.0f / s;
    ((float4*)&dst[(size_t)row*512])[threadIdx.x]
        = make_float4(e0*inv, e1*inv, e2*inv, e3*inv);
}

// =====================================================================
// Context GEMMs (merged):
//  which=0: c12[b,m,d] = sum_l d12 [b,l,m] * ctx1[l,b,d]
//  which=1: c21[b,l,d] = sum_m d21t[b,m,l] * ctx2[m,b,d]
// Both read A transposed (k-major rows), identical access pattern.
// grid (256/64, 512/64, 2*BB), 256 threads
// =====================================================================
__global__ __launch_bounds__(256) void context_kernel(
    const float* __restrict__ ctx1, const float* __restrict__ ctx2)
{
    const int which = blockIdx.z >> 1;
    const int b     = blockIdx.z & 1;
    const float* Asrc = which ? g_d21t : g_d12;
    const float* Bsrc = which ? ctx2   : ctx1;
    float*       Cdst = which ? g_c21  : g_c12;
    const int i0 = blockIdx.y * 64;
    const int j0 = blockIdx.x * 64;
    const int tid = threadIdx.x;
    __shared__ float As[16][68];
    __shared__ float Bs[16][64];
    float acc[4][4] = {};
    const int ak = tid >> 4, am = (tid & 15) << 2;
    const int bk = tid >> 4, bj = (tid & 15) << 2;
    const int ti = (tid >> 4) << 2, tj = (tid & 15) << 2;

    for (int k0 = 0; k0 < L1N; k0 += 16) {
        *(float4*)&As[ak][am]
            = *(const float4*)&Asrc[((size_t)(b*L1N)+(k0+ak))*L2N + i0 + am];
        *(float4*)&Bs[bk][bj]
            = *(const float4*)&Bsrc[((size_t)(k0+bk)*BB + b)*D1N + j0 + bj];
        __syncthreads();
        #pragma unroll
        for (int k = 0; k < 16; ++k) {
            const float4 a = *(const float4*)&As[k][ti];
            const float4 w = *(const float4*)&Bs[k][tj];
            const float ar[4]={a.x,a.y,a.z,a.w}, br[4]={w.x,w.y,w.z,w.w};
            #pragma unroll
            for (int r=0;r<4;r++)
                #pragma unroll
                for (int c=0;c<4;c++)
                    acc[r][c] = fmaf(ar[r], br[c], acc[r][c]);
        }
        __syncthreads();
    }
    #pragma unroll
    for (int r=0;r<4;r++)
        *(float4*)&Cdst[((size_t)(b*L1N)+(i0+ti+r))*D1N + j0 + tj]
            = make_float4(acc[r][0],acc[r][1],acc[r][2],acc[r][3]);
}

// =====================================================================
// Output GEMMs (merged) + epilogue tanh + scatter:
//  which=0: seq_2_to_1[l,b,:] = tanh(q1 + c21 @ W21[D1:] + b21) -> out[0..]
//  which=1: seq_1_to_2[m,b,:] = tanh(q2 + c12 @ W12[D2:] + b12) -> out[L1*B*BN..]
// grid (256/64, 1024/64, 2), 256 threads
// =====================================================================
__global__ __launch_bounds__(256) void out_kernel(
    const float* __restrict__ W12, const float* __restrict__ b12,
    const float* __restrict__ W21, const float* __restrict__ b21,
    float* __restrict__ out)
{
    const int which = blockIdx.z;
    const float* A    = which ? g_c12 : g_c21;
    const float* Bm   = which ? (W12 + (size_t)D2N*BNN) : (W21 + (size_t)D1N*BNN);
    const float* bias = which ? b12 : b21;
    const float* Q    = which ? g_q2 : g_q1;
    float* O          = out + (which ? (size_t)L1N*BB*BNN : 0);
    const int i0 = blockIdx.y * 64;
    const int j0 = blockIdx.x * 64;
    const int tid = threadIdx.x;
    __shared__ float As[16][68];
    __shared__ float Bs[16][64];
    float acc[4][4] = {};
    const int ai = tid >> 2, ad = (tid & 3) << 2;
    const int bk = tid >> 4, bj = (tid & 15) << 2;
    const int ti = (tid >> 4) << 2, tj = (tid & 15) << 2;

    for (int k0 = 0; k0 < D1N; k0 += 16) {
        float4 av = *(const float4*)&A[(size_t)(i0+ai)*D1N + k0 + ad];
        As[ad+0][ai]=av.x; As[ad+1][ai]=av.y; As[ad+2][ai]=av.z; As[ad+3][ai]=av.w;
        *(float4*)&Bs[bk][bj] = *(const float4*)&Bm[(size_t)(k0+bk)*BNN + j0 + bj];
        __syncthreads();
        #pragma unroll
        for (int k = 0; k < 16; ++k) {
            const float4 a = *(const float4*)&As[k][ti];
            const float4 w = *(const float4*)&Bs[k][tj];
            const float ar[4]={a.x,a.y,a.z,a.w}, br[4]={w.x,w.y,w.z,w.w};
            #pragma unroll
            for (int r=0;r<4;r++)
                #pragma unroll
                for (int c=0;c<4;c++)
                    acc[r][c] = fmaf(ar[r], br[c], acc[r][c]);
        }
        __syncthreads();
    }
    const float4 bb = *(const float4*)&bias[j0+tj];
    #pragma unroll
    for (int r=0;r<4;r++){
        const int row = i0+ti+r;              // row = b*512 + seqpos
        const int b = row >> 9, sp = row & 511;
        const float4 q = *(const float4*)&Q[(size_t)row*BNN + j0 + tj];
        float4 o;
        o.x = tanhf(acc[r][0]+q.x+bb.x);
        o.y = tanhf(acc[r][1]+q.y+bb.y);
        o.z = tanhf(acc[r][2]+q.z+bb.z);
        o.w = tanhf(acc[r][3]+q.w+bb.w);
        *(float4*)&O[((size_t)(sp*BB)+b)*BNN + j0 + tj] = o;
    }
}

// =====================================================================
extern "C" void kernel_launch(void* const* d_in, const int* in_sizes, int n_in,
                              void* d_out, int out_size)
{
    (void)in_sizes; (void)n_in; (void)out_size;
    const float* ctx1 = (const float*)d_in[0];
    const float* ctx2 = (const float*)d_in[1];
    const float* m1   = (const float*)d_in[2];
    const float* m2   = (const float*)d_in[3];
    const float* Wh   = (const float*)d_in[4];
    const float* bh   = (const float*)d_in[5];
    const float* wo   = (const float*)d_in[6];
    const float* W12  = (const float*)d_in[7];
    const float* b12  = (const float*)d_in[8];
    const float* W21  = (const float*)d_in[9];
    const float* b21  = (const float*)d_in[10];
    float* out = (float*)d_out;

    proj4_kernel       <<<dim3(BNN/64, L1N/64, 4*BB), 256>>>(ctx1, ctx2, Wh, bh, W12, W21);
    affinity_kernel    <<<dim3(L2N/64, L1N/64, BB),   256>>>(m1, m2, wo);
    softmax_dual_kernel<<<dim3(BB*L1N, 2), 128>>>();
    context_kernel     <<<dim3(D1N/64, L2N/64, 2*BB), 256>>>(ctx1, ctx2);
    out_kernel         <<<dim3(BNN/64, (BB*L1N)/64, 2), 256>>>(W12, b12, W21, b21, out);
}

// round 3
// speedup vs baseline: 1.4656x; 1.1875x over previous
#include <cuda_runtime.h>

#define L1N 512
#define L2N 512
#define BB  2
#define D1N 256
#define D2N 256
#define BNN 256
#define NEGC (-1.0e12f)

typedef unsigned long long u64;

// ---------------- device scratch (no allocations allowed) ----------------
__device__ float g_p1[BB*L1N*BNN];    // [b][l][k]
__device__ float g_p2[BB*L2N*BNN];    // [b][m][k] (+bh)
__device__ float g_q1[BB*L1N*BNN];    // [b][l][k]
__device__ float g_q2[BB*L2N*BNN];    // [b][m][k]
__device__ float g_aff [BB*L1N*L2N];  // [b][l][m]
__device__ float g_afft[BB*L2N*L1N];  // [b][m][l]
__device__ float g_d12 [BB*L1N*L2N];  // softmax over m      [b][l][m]
__device__ float g_d21t[BB*L2N*L1N];  // softmax over l, T'd [b][m][l]
__device__ float g_c12[BB*L2N*D1N];   // [b][m][d]
__device__ float g_c21[BB*L1N*D2N];   // [b][l][d]

__device__ __forceinline__ float tanh_fast(float x){
    float y; asm("tanh.approx.f32 %0, %1;" : "=f"(y) : "f"(x)); return y;
}
__device__ __forceinline__ u64 pack2(float v){
    u64 r; unsigned u = __float_as_uint(v);
    asm("mov.b64 %0, {%1, %2};" : "=l"(r) : "r"(u), "r"(u)); return r;
}
__device__ __forceinline__ u64 fma2(u64 a, u64 b, u64 c){
    u64 d; asm("fma.rn.f32x2 %0, %1, %2, %3;" : "=l"(d) : "l"(a), "l"(b), "l"(c));
    return d;
}
__device__ __forceinline__ float2 unpack2(u64 v){
    unsigned lo, hi;
    asm("mov.b64 {%0, %1}, %2;" : "=r"(lo), "=r"(hi) : "l"(v));
    return make_float2(__uint_as_float(lo), __uint_as_float(hi));
}

// 8×fma2 + 4 packs inner step on one k-slice of the 4x4 (as 4x2-pair) tile
#define FMA2_STEP(As_, Bs_, kk_)                                            \
    {                                                                        \
        const float4 a = *(const float4*)&As_[kk_][ti];                      \
        const ulonglong2 bb = *(const ulonglong2*)&Bs_[kk_][tj];             \
        const u64 a0 = pack2(a.x), a1 = pack2(a.y),                          \
                  a2 = pack2(a.z), a3 = pack2(a.w);                          \
        acc[0][0]=fma2(a0,bb.x,acc[0][0]); acc[0][1]=fma2(a0,bb.y,acc[0][1]);\
        acc[1][0]=fma2(a1,bb.x,acc[1][0]); acc[1][1]=fma2(a1,bb.y,acc[1][1]);\
        acc[2][0]=fma2(a2,bb.x,acc[2][0]); acc[2][1]=fma2(a2,bb.y,acc[2][1]);\
        acc[3][0]=fma2(a3,bb.x,acc[3][0]); acc[3][1]=fma2(a3,bb.y,acc[3][1]);\
    }

// =====================================================================
// Projections: 4 GEMMs (512x256 @ 256x256 per b), one launch.
// grid (BNN/64, 512/64, 4*BB), 256 threads, double-buffered, f32x2.
// =====================================================================
__global__ __launch_bounds__(256) void proj4_kernel(
    const float* __restrict__ ctx1, const float* __restrict__ ctx2,
    const float* __restrict__ Wh,  const float* __restrict__ bh,
    const float* __restrict__ W12, const float* __restrict__ W21)
{
    const int mode = blockIdx.z >> 1;
    const int b    = blockIdx.z & 1;
    const float* X; const float* W; const float* bias; float* P;
    if (mode == 0)      { X = ctx1; W = Wh;             bias = nullptr; P = g_p1; }
    else if (mode == 1) { X = ctx2; W = Wh + D1N*BNN;   bias = bh;      P = g_p2; }
    else if (mode == 2) { X = ctx2; W = W12;            bias = nullptr; P = g_q2; }
    else                { X = ctx1; W = W21;            bias = nullptr; P = g_q1; }

    const int i0 = blockIdx.y * 64;
    const int j0 = blockIdx.x * 64;
    const int tid = threadIdx.x;
    __shared__ __align__(16) float As[2][16][68];
    __shared__ __align__(16) float Bs[2][16][64];
    u64 acc[4][2] = {};
    const int ai = tid >> 2, ad = (tid & 3) << 2;
    const int bk = tid >> 4, bj = (tid & 15) << 2;
    const int ti = (tid >> 4) << 2, tj = (tid & 15) << 2;

    const size_t arow = ((size_t)(i0+ai)*BB + b)*D1N + ad;
    float4 rA = *(const float4*)&X[arow];
    float4 rB = *(const float4*)&W[(size_t)bk*BNN + j0 + bj];
    As[0][ad+0][ai]=rA.x; As[0][ad+1][ai]=rA.y; As[0][ad+2][ai]=rA.z; As[0][ad+3][ai]=rA.w;
    *(float4*)&Bs[0][bk][bj] = rB;
    __syncthreads();

    const int T = D1N/16;
    #pragma unroll 1
    for (int t = 0; t < T; ++t) {
        const int cur = t & 1;
        if (t+1 < T) {
            rA = *(const float4*)&X[arow + (t+1)*16];
            rB = *(const float4*)&W[(size_t)((t+1)*16+bk)*BNN + j0 + bj];
        }
        #pragma unroll
        for (int k = 0; k < 16; ++k) FMA2_STEP(As[cur], Bs[cur], k);
        if (t+1 < T) {
            const int nxt = cur ^ 1;
            As[nxt][ad+0][ai]=rA.x; As[nxt][ad+1][ai]=rA.y;
            As[nxt][ad+2][ai]=rA.z; As[nxt][ad+3][ai]=rA.w;
            *(float4*)&Bs[nxt][bk][bj] = rB;
            __syncthreads();
        }
    }
    float4 bb = bias ? *(const float4*)&bias[j0+tj] : make_float4(0.f,0.f,0.f,0.f);
    #pragma unroll
    for (int r=0;r<4;r++){
        float2 lo = unpack2(acc[r][0]), hi = unpack2(acc[r][1]);
        float4 o = make_float4(lo.x+bb.x, lo.y+bb.y, hi.x+bb.z, hi.y+bb.w);
        *(float4*)&P[((size_t)(b*L1N)+(i0+ti+r))*BNN + j0 + tj] = o;
    }
}

// =====================================================================
// Affinity: aff[b,l,m] = sum_k wo[k]*tanh(p1[b,l,k]+p2[b,m,k]) + masks.
// Dual store (row-major + transposed). MUFU-bound; double-buffered loads.
// grid (L2/64, L1/64, B), 256 threads.
// =====================================================================
__global__ __launch_bounds__(256) void affinity_kernel(
    const float* __restrict__ m1, const float* __restrict__ m2,
    const float* __restrict__ wo)
{
    const int b  = blockIdx.z;
    const int l0 = blockIdx.y * 64;
    const int m0 = blockIdx.x * 64;
    const int tid = threadIdx.x;
    __shared__ __align__(16) float P1s[2][16][68];
    __shared__ __align__(16) float P2s[2][16][68];
    __shared__ float wos[BNN];
    wos[tid] = wo[tid];
    float acc[4][4] = {};
    const int ai = tid >> 2, ad = (tid & 3) << 2;
    const int ti = (tid >> 4) << 2, tm = (tid & 15) << 2;

    const size_t prow1 = ((size_t)(b*L1N)+(l0+ai))*BNN + ad;
    const size_t prow2 = ((size_t)(b*L2N)+(m0+ai))*BNN + ad;
    float4 rA = *(const float4*)&g_p1[prow1];
    float4 rB = *(const float4*)&g_p2[prow2];
    P1s[0][ad+0][ai]=rA.x; P1s[0][ad+1][ai]=rA.y; P1s[0][ad+2][ai]=rA.z; P1s[0][ad+3][ai]=rA.w;
    P2s[0][ad+0][ai]=rB.x; P2s[0][ad+1][ai]=rB.y; P2s[0][ad+2][ai]=rB.z; P2s[0][ad+3][ai]=rB.w;
    __syncthreads();

    const int T = BNN/16;
    #pragma unroll 1
    for (int t = 0; t < T; ++t) {
        const int cur = t & 1;
        if (t+1 < T) {
            rA = *(const float4*)&g_p1[prow1 + (t+1)*16];
            rB = *(const float4*)&g_p2[prow2 + (t+1)*16];
        }
        #pragma unroll
        for (int kk = 0; kk < 16; ++kk) {
            const float w = wos[t*16+kk];
            const float4 av = *(const float4*)&P1s[cur][kk][ti];
            const float4 cv = *(const float4*)&P2s[cur][kk][tm];
            const float ar[4]={av.x,av.y,av.z,av.w}, cr[4]={cv.x,cv.y,cv.z,cv.w};
            #pragma unroll
            for (int r=0;r<4;r++)
                #pragma unroll
                for (int c=0;c<4;c++)
                    acc[r][c] = fmaf(w, tanh_fast(ar[r]+cr[c]), acc[r][c]);
        }
        if (t+1 < T) {
            const int nxt = cur ^ 1;
            P1s[nxt][ad+0][ai]=rA.x; P1s[nxt][ad+1][ai]=rA.y;
            P1s[nxt][ad+2][ai]=rA.z; P1s[nxt][ad+3][ai]=rA.w;
            P2s[nxt][ad+0][ai]=rB.x; P2s[nxt][ad+1][ai]=rB.y;
            P2s[nxt][ad+2][ai]=rB.z; P2s[nxt][ad+3][ai]=rB.w;
            __syncthreads();
        }
    }
    float mrow[4], mcol[4];
    #pragma unroll
    for (int r=0;r<4;r++) mrow[r] = (1.0f - m1[(l0+ti+r)*BB + b]) * NEGC;
    #pragma unroll
    for (int c=0;c<4;c++) mcol[c] = (1.0f - m2[(m0+tm+c)*BB + b]) * NEGC;
    #pragma unroll
    for (int r=0;r<4;r++)
        #pragma unroll
        for (int c=0;c<4;c++)
            acc[r][c] += mrow[r] + mcol[c];
    #pragma unroll
    for (int r=0;r<4;r++)
        *(float4*)&g_aff[((size_t)(b*L1N)+(l0+ti+r))*L2N + m0 + tm]
            = make_float4(acc[r][0],acc[r][1],acc[r][2],acc[r][3]);
    #pragma unroll
    for (int c=0;c<4;c++)
        *(float4*)&g_afft[((size_t)(b*L2N)+(m0+tm+c))*L1N + l0 + ti]
            = make_float4(acc[0][c],acc[1][c],acc[2][c],acc[3][c]);
}

// =====================================================================
// Dual row softmax: grid (B*512, 2); y=0: g_aff->g_d12, y=1: g_afft->g_d21t
// =====================================================================
__global__ __launch_bounds__(128) void softmax_dual_kernel()
{
    const int row = blockIdx.x;
    const float* src = blockIdx.y ? g_afft : g_aff;
    float*       dst = blockIdx.y ? g_d21t : g_d12;
    const float4 v = ((const float4*)&src[(size_t)row*512])[threadIdx.x];
    float mx = fmaxf(fmaxf(v.x,v.y), fmaxf(v.z,v.w));
    #pragma unroll
    for (int o=16;o;o>>=1) mx = fmaxf(mx, __shfl_xor_sync(0xffffffffu, mx, o));
    __shared__ float redm[4], reds[4];
    const int wid = threadIdx.x >> 5, lane = threadIdx.x & 31;
    if (!lane) redm[wid] = mx;
    __syncthreads();
    mx = fmaxf(fmaxf(redm[0],redm[1]), fmaxf(redm[2],redm[3]));
    float e0=__expf(v.x-mx), e1=__expf(v.y-mx), e2=__expf(v.z-mx), e3=__expf(v.w-mx);
    float s = (e0+e1)+(e2+e3);
    #pragma unroll
    for (int o=16;o;o>>=1) s += __shfl_xor_sync(0xffffffffu, s, o);
    if (!lane) reds[wid] = s;
    __syncthreads();
    s = (reds[0]+reds[1])+(reds[2]+reds[3]);
    const float inv = 1.0f / s;
    ((float4*)&dst[(size_t)row*512])[threadIdx.x]
        = make_float4(e0*inv, e1*inv, e2*inv, e3*inv);
}

// =====================================================================
// Context GEMMs (merged), K=512, double-buffered, f32x2:
//  which=0: c12[b,m,d] = sum_l d12 [b,l,m] * ctx1[l,b,d]
//  which=1: c21[b,l,d] = sum_m d21t[b,m,l] * ctx2[m,b,d]
// grid (256/64, 512/64, 2*BB), 256 threads
// =====================================================================
__global__ __launch_bounds__(256) void context_kernel(
    const float* __restrict__ ctx1, const float* __restrict__ ctx2)
{
    const int which = blockIdx.z >> 1;
    const int b     = blockIdx.z & 1;
    const float* Asrc = which ? g_d21t : g_d12;
    const float* Bsrc = which ? ctx2   : ctx1;
    float*       Cdst = which ? g_c21  : g_c12;
    const int i0 = blockIdx.y * 64;
    const int j0 = blockIdx.x * 64;
    const int tid = threadIdx.x;
    __shared__ __align__(16) float As[2][16][68];
    __shared__ __align__(16) float Bs[2][16][64];
    u64 acc[4][2] = {};
    const int ak = tid >> 4, am = (tid & 15) << 2;
    const int bk = tid >> 4, bj = (tid & 15) << 2;
    const int ti = (tid >> 4) << 2, tj = (tid & 15) << 2;

    float4 rA = *(const float4*)&Asrc[((size_t)(b*L1N)+ak)*L2N + i0 + am];
    float4 rB = *(const float4*)&Bsrc[((size_t)bk*BB + b)*D1N + j0 + bj];
    *(float4*)&As[0][ak][am] = rA;
    *(float4*)&Bs[0][bk][bj] = rB;
    __syncthreads();

    const int T = L1N/16;
    #pragma unroll 1
    for (int t = 0; t < T; ++t) {
        const int cur = t & 1;
        if (t+1 < T) {
            rA = *(const float4*)&Asrc[((size_t)(b*L1N)+((t+1)*16+ak))*L2N + i0 + am];
            rB = *(const float4*)&Bsrc[((size_t)((t+1)*16+bk)*BB + b)*D1N + j0 + bj];
        }
        #pragma unroll
        for (int k = 0; k < 16; ++k) FMA2_STEP(As[cur], Bs[cur], k);
        if (t+1 < T) {
            const int nxt = cur ^ 1;
            *(float4*)&As[nxt][ak][am] = rA;
            *(float4*)&Bs[nxt][bk][bj] = rB;
            __syncthreads();
        }
    }
    #pragma unroll
    for (int r=0;r<4;r++){
        float2 lo = unpack2(acc[r][0]), hi = unpack2(acc[r][1]);
        *(float4*)&Cdst[((size_t)(b*L1N)+(i0+ti+r))*D1N + j0 + tj]
            = make_float4(lo.x,lo.y,hi.x,hi.y);
    }
}

// =====================================================================
// Output GEMMs (merged) + tanh epilogue + scatter, double-buffered, f32x2:
//  which=0: seq_2_to_1 = tanh(q1 + c21 @ W21[D1:] + b21) -> out[0..]
//  which=1: seq_1_to_2 = tanh(q2 + c12 @ W12[D2:] + b12) -> out[L1*B*BN..]
// grid (256/64, 1024/64, 2), 256 threads
// =====================================================================
__global__ __launch_bounds__(256) void out_kernel(
    const float* __restrict__ W12, const float* __restrict__ b12,
    const float* __restrict__ W21, const float* __restrict__ b21,
    float* __restrict__ out)
{
    const int which = blockIdx.z;
    const float* A    = which ? g_c12 : g_c21;
    const float* Bm   = which ? (W12 + (size_t)D2N*BNN) : (W21 + (size_t)D1N*BNN);
    const float* bias = which ? b12 : b21;
    const float* Q    = which ? g_q2 : g_q1;
    float* O          = out + (which ? (size_t)L1N*BB*BNN : 0);
    const int i0 = blockIdx.y * 64;
    const int j0 = blockIdx.x * 64;
    const int tid = threadIdx.x;
    __shared__ __align__(16) float As[2][16][68];
    __shared__ __align__(16) float Bs[2][16][64];
    u64 acc[4][2] = {};
    const int ai = tid >> 2, ad = (tid & 3) << 2;
    const int bk = tid >> 4, bj = (tid & 15) << 2;
    const int ti = (tid >> 4) << 2, tj = (tid & 15) << 2;

    const size_t arow = (size_t)(i0+ai)*D1N + ad;
    float4 rA = *(const float4*)&A[arow];
    float4 rB = *(const float4*)&Bm[(size_t)bk*BNN + j0 + bj];
    As[0][ad+0][ai]=rA.x; As[0][ad+1][ai]=rA.y; As[0][ad+2][ai]=rA.z; As[0][ad+3][ai]=rA.w;
    *(float4*)&Bs[0][bk][bj] = rB;
    __syncthreads();

    const int T = D1N/16;
    #pragma unroll 1
    for (int t = 0; t < T; ++t) {
        const int cur = t & 1;
        if (t+1 < T) {
            rA = *(const float4*)&A[arow + (t+1)*16];
            rB = *(const float4*)&Bm[(size_t)((t+1)*16+bk)*BNN + j0 + bj];
        }
        #pragma unroll
        for (int k = 0; k < 16; ++k) FMA2_STEP(As[cur], Bs[cur], k);
        if (t+1 < T) {
            const int nxt = cur ^ 1;
            As[nxt][ad+0][ai]=rA.x; As[nxt][ad+1][ai]=rA.y;
            As[nxt][ad+2][ai]=rA.z; As[nxt][ad+3][ai]=rA.w;
            *(float4*)&Bs[nxt][bk][bj] = rB;
            __syncthreads();
        }
    }
    const float4 bb = *(const float4*)&bias[j0+tj];
    #pragma unroll
    for (int r=0;r<4;r++){
        const int row = i0+ti+r;              // row = b*512 + seqpos
        const int b = row >> 9, sp = row & 511;
        const float4 q = *(const float4*)&Q[(size_t)row*BNN + j0 + tj];
        float2 lo = unpack2(acc[r][0]), hi = unpack2(acc[r][1]);
        float4 o;
        o.x = tanhf(lo.x+q.x+bb.x);
        o.y = tanhf(lo.y+q.y+bb.y);
        o.z = tanhf(hi.x+q.z+bb.z);
        o.w = tanhf(hi.y+q.w+bb.w);
        *(float4*)&O[((size_t)(sp*BB)+b)*BNN + j0 + tj] = o;
    }
}

// =====================================================================
extern "C" void kernel_launch(void* const* d_in, const int* in_sizes, int n_in,
                              void* d_out, int out_size)
{
    (void)in_sizes; (void)n_in; (void)out_size;
    const float* ctx1 = (const float*)d_in[0];
    const float* ctx2 = (const float*)d_in[1];
    const float* m1   = (const float*)d_in[2];
    const float* m2   = (const float*)d_in[3];
    const float* Wh   = (const float*)d_in[4];
    const float* bh   = (const float*)d_in[5];
    const float* wo   = (const float*)d_in[6];
    const float* W12  = (const float*)d_in[7];
    const float* b12  = (const float*)d_in[8];
    const float* W21  = (const float*)d_in[9];
    const float* b21  = (const float*)d_in[10];
    float* out = (float*)d_out;

    proj4_kernel       <<<dim3(BNN/64, L1N/64, 4*BB), 256>>>(ctx1, ctx2, Wh, bh, W12, W21);
    affinity_kernel    <<<dim3(L2N/64, L1N/64, BB),   256>>>(m1, m2, wo);
    softmax_dual_kernel<<<dim3(BB*L1N, 2), 128>>>();
    context_kernel     <<<dim3(D1N/64, L2N/64, 2*BB), 256>>>(ctx1, ctx2);
    out_kernel         <<<dim3(BNN/64, (BB*L1N)/64, 2), 256>>>(W12, b12, W21, b21, out);
}

// round 4
// speedup vs baseline: 1.4696x; 1.0028x over previous
#include <cuda_runtime.h>

#define L1N 512
#define L2N 512
#define BB  2
#define D1N 256
#define D2N 256
#define BNN 256
#define NEGC (-1.0e12f)

typedef unsigned long long u64;

// ---------------- device scratch (no allocations allowed) ----------------
__device__ float g_p1h[2][BB*L1N*BNN];   // K-split halves of p1 [b][l][k]
__device__ float g_p2h[2][BB*L2N*BNN];   // K-split halves of p2 (+bh in half 0)
__device__ float g_q1[BB*L1N*BNN];       // [b][l][k]
__device__ float g_q2[BB*L2N*BNN];       // [b][m][k]
__device__ float g_aff [BB*L1N*L2N];     // [b][l][m]
__device__ float g_afft[BB*L2N*L1N];     // [b][m][l]
__device__ float g_d12 [BB*L1N*L2N];     // softmax over m      [b][l][m]
__device__ float g_d21t[BB*L2N*L1N];     // softmax over l, T'd [b][m][l]
__device__ float g_c12h[2][BB*L2N*D1N];  // K-split halves [b][m][d]
__device__ float g_c21h[2][BB*L1N*D2N];  // K-split halves [b][l][d]

__device__ __forceinline__ float tanh_fast(float x){
    float y; asm("tanh.approx.f32 %0, %1;" : "=f"(y) : "f"(x)); return y;
}
__device__ __forceinline__ u64 pack2(float v){
    u64 r; unsigned u = __float_as_uint(v);
    asm("mov.b64 %0, {%1, %2};" : "=l"(r) : "r"(u), "r"(u)); return r;
}
__device__ __forceinline__ u64 fma2(u64 a, u64 b, u64 c){
    u64 d; asm("fma.rn.f32x2 %0, %1, %2, %3;" : "=l"(d) : "l"(a), "l"(b), "l"(c));
    return d;
}
__device__ __forceinline__ float2 unpack2(u64 v){
    unsigned lo, hi;
    asm("mov.b64 {%0, %1}, %2;" : "=r"(lo), "=r"(hi) : "l"(v));
    return make_float2(__uint_as_float(lo), __uint_as_float(hi));
}
__device__ __forceinline__ float4 f4add(float4 a, float4 b){
    return make_float4(a.x+b.x, a.y+b.y, a.z+b.z, a.w+b.w);
}

// 8×fma2 inner step on one k-slice of the 4x4 (as 4x2-pair) tile
#define FMA2_STEP(As_, Bs_, kk_)                                            \
    {                                                                        \
        const float4 a = *(const float4*)&As_[kk_][ti];                      \
        const ulonglong2 bb = *(const ulonglong2*)&Bs_[kk_][tj];             \
        const u64 a0 = pack2(a.x), a1 = pack2(a.y),                          \
                  a2 = pack2(a.z), a3 = pack2(a.w);                          \
        acc[0][0]=fma2(a0,bb.x,acc[0][0]); acc[0][1]=fma2(a0,bb.y,acc[0][1]);\
        acc[1][0]=fma2(a1,bb.x,acc[1][0]); acc[1][1]=fma2(a1,bb.y,acc[1][1]);\
        acc[2][0]=fma2(a2,bb.x,acc[2][0]); acc[2][1]=fma2(a2,bb.y,acc[2][1]);\
        acc[3][0]=fma2(a3,bb.x,acc[3][0]); acc[3][1]=fma2(a3,bb.y,acc[3][1]);\
    }

// =====================================================================
// p-projections, K-split 2x:
//  mode0: p1 = ctx1 @ Wh[:D1]      mode1: p2 = ctx2 @ Wh[D1:] (+bh, half 0)
// grid (4, 8, 8): x=j0, y=i0, z = mode*4 + b*2 + ks. 256 threads.
// =====================================================================
__global__ __launch_bounds__(256) void proj_p_kernel(
    const float* __restrict__ ctx1, const float* __restrict__ ctx2,
    const float* __restrict__ Wh,  const float* __restrict__ bh)
{
    const int mode = blockIdx.z >> 2;
    const int b    = (blockIdx.z >> 1) & 1;
    const int ks   = blockIdx.z & 1;
    const float* X = mode ? ctx2 : ctx1;
    const float* W = mode ? (Wh + (size_t)D1N*BNN) : Wh;
    float* P       = mode ? g_p2h[ks] : g_p1h[ks];
    const bool addb = (mode == 1) && (ks == 0);

    const int i0 = blockIdx.y * 64;
    const int j0 = blockIdx.x * 64;
    const int k00 = ks * 128;
    const int tid = threadIdx.x;
    __shared__ __align__(16) float As[2][16][68];
    __shared__ __align__(16) float Bs[2][16][64];
    u64 acc[4][2] = {};
    const int ai = tid >> 2, ad = (tid & 3) << 2;
    const int bk = tid >> 4, bj = (tid & 15) << 2;
    const int ti = (tid >> 4) << 2, tj = (tid & 15) << 2;

    const size_t arow = ((size_t)(i0+ai)*BB + b)*D1N + k00 + ad;
    float4 rA = *(const float4*)&X[arow];
    float4 rB = *(const float4*)&W[(size_t)(k00+bk)*BNN + j0 + bj];
    As[0][ad+0][ai]=rA.x; As[0][ad+1][ai]=rA.y; As[0][ad+2][ai]=rA.z; As[0][ad+3][ai]=rA.w;
    *(float4*)&Bs[0][bk][bj] = rB;
    __syncthreads();

    const int T = 128/16;
    #pragma unroll 1
    for (int t = 0; t < T; ++t) {
        const int cur = t & 1;
        if (t+1 < T) {
            rA = *(const float4*)&X[arow + (t+1)*16];
            rB = *(const float4*)&W[(size_t)(k00+(t+1)*16+bk)*BNN + j0 + bj];
        }
        #pragma unroll
        for (int k = 0; k < 16; ++k) FMA2_STEP(As[cur], Bs[cur], k);
        if (t+1 < T) {
            const int nxt = cur ^ 1;
            As[nxt][ad+0][ai]=rA.x; As[nxt][ad+1][ai]=rA.y;
            As[nxt][ad+2][ai]=rA.z; As[nxt][ad+3][ai]=rA.w;
            *(float4*)&Bs[nxt][bk][bj] = rB;
            __syncthreads();
        }
    }
    float4 bb = addb ? *(const float4*)&bh[j0+tj] : make_float4(0.f,0.f,0.f,0.f);
    #pragma unroll
    for (int r=0;r<4;r++){
        float2 lo = unpack2(acc[r][0]), hi = unpack2(acc[r][1]);
        float4 o = make_float4(lo.x+bb.x, lo.y+bb.y, hi.x+bb.z, hi.y+bb.w);
        *(float4*)&P[((size_t)(b*L1N)+(i0+ti+r))*BNN + j0 + tj] = o;
    }
}

// =====================================================================
// Heterogeneous: affinity (z=0,1) + q-projections (z=2: q1, z=3: q2).
// grid (8, 8, 4), 256 threads.
// Affinity: aff[b,l,m] = sum_k wo[k]*tanh(p1+p2) + masks; dual store.
// q-proj: q1 = ctx1 @ W21[:D1], q2 = ctx2 @ W12[:D2]; full K=256.
// =====================================================================
__global__ __launch_bounds__(256) void affinity_q_kernel(
    const float* __restrict__ ctx1, const float* __restrict__ ctx2,
    const float* __restrict__ m1, const float* __restrict__ m2,
    const float* __restrict__ wo,
    const float* __restrict__ W12, const float* __restrict__ W21)
{
    const int tid = threadIdx.x;
    if (blockIdx.z >= 2) {
        // ---------------- q-projection path ----------------
        const int qmode = blockIdx.z - 2;          // 0: q1, 1: q2
        const float* X = qmode ? ctx2 : ctx1;
        const float* W = qmode ? W12  : W21;
        float* P       = qmode ? g_q2 : g_q1;
        const int b  = blockIdx.x >> 2;
        const int j0 = (blockIdx.x & 3) * 64;
        const int i0 = blockIdx.y * 64;
        __shared__ __align__(16) float As[2][16][68];
        __shared__ __align__(16) float Bs[2][16][64];
        u64 acc[4][2] = {};
        const int ai = tid >> 2, ad = (tid & 3) << 2;
        const int bk = tid >> 4, bj = (tid & 15) << 2;
        const int ti = (tid >> 4) << 2, tj = (tid & 15) << 2;

        const size_t arow = ((size_t)(i0+ai)*BB + b)*D1N + ad;
        float4 rA = *(const float4*)&X[arow];
        float4 rB = *(const float4*)&W[(size_t)bk*BNN + j0 + bj];
        As[0][ad+0][ai]=rA.x; As[0][ad+1][ai]=rA.y; As[0][ad+2][ai]=rA.z; As[0][ad+3][ai]=rA.w;
        *(float4*)&Bs[0][bk][bj] = rB;
        __syncthreads();

        const int T = D1N/16;
        #pragma unroll 1
        for (int t = 0; t < T; ++t) {
            const int cur = t & 1;
            if (t+1 < T) {
                rA = *(const float4*)&X[arow + (t+1)*16];
                rB = *(const float4*)&W[(size_t)((t+1)*16+bk)*BNN + j0 + bj];
            }
            #pragma unroll
            for (int k = 0; k < 16; ++k) FMA2_STEP(As[cur], Bs[cur], k);
            if (t+1 < T) {
                const int nxt = cur ^ 1;
                As[nxt][ad+0][ai]=rA.x; As[nxt][ad+1][ai]=rA.y;
                As[nxt][ad+2][ai]=rA.z; As[nxt][ad+3][ai]=rA.w;
                *(float4*)&Bs[nxt][bk][bj] = rB;
                __syncthreads();
            }
        }
        #pragma unroll
        for (int r=0;r<4;r++){
            float2 lo = unpack2(acc[r][0]), hi = unpack2(acc[r][1]);
            *(float4*)&P[((size_t)(b*L1N)+(i0+ti+r))*BNN + j0 + tj]
                = make_float4(lo.x,lo.y,hi.x,hi.y);
        }
        return;
    }
    // ---------------- affinity path ----------------
    const int b  = blockIdx.z;
    const int l0 = blockIdx.y * 64;
    const int m0 = blockIdx.x * 64;
    __shared__ __align__(16) float P1s[2][16][68];
    __shared__ __align__(16) float P2s[2][16][68];
    __shared__ float wos[BNN];
    wos[tid] = wo[tid];
    float acc[4][4] = {};
    const int ai = tid >> 2, ad = (tid & 3) << 2;
    const int ti = (tid >> 4) << 2, tm = (tid & 15) << 2;

    const size_t prow1 = ((size_t)(b*L1N)+(l0+ai))*BNN + ad;
    const size_t prow2 = ((size_t)(b*L2N)+(m0+ai))*BNN + ad;
    float4 rA = f4add(*(const float4*)&g_p1h[0][prow1],
                      *(const float4*)&g_p1h[1][prow1]);
    float4 rB = f4add(*(const float4*)&g_p2h[0][prow2],
                      *(const float4*)&g_p2h[1][prow2]);
    P1s[0][ad+0][ai]=rA.x; P1s[0][ad+1][ai]=rA.y; P1s[0][ad+2][ai]=rA.z; P1s[0][ad+3][ai]=rA.w;
    P2s[0][ad+0][ai]=rB.x; P2s[0][ad+1][ai]=rB.y; P2s[0][ad+2][ai]=rB.z; P2s[0][ad+3][ai]=rB.w;
    __syncthreads();

    const int T = BNN/16;
    #pragma unroll 1
    for (int t = 0; t < T; ++t) {
        const int cur = t & 1;
        if (t+1 < T) {
            rA = f4add(*(const float4*)&g_p1h[0][prow1 + (t+1)*16],
                       *(const float4*)&g_p1h[1][prow1 + (t+1)*16]);
            rB = f4add(*(const float4*)&g_p2h[0][prow2 + (t+1)*16],
                       *(const float4*)&g_p2h[1][prow2 + (t+1)*16]);
        }
        #pragma unroll
        for (int kk = 0; kk < 16; ++kk) {
            const float w = wos[t*16+kk];
            const float4 av = *(const float4*)&P1s[cur][kk][ti];
            const float4 cv = *(const float4*)&P2s[cur][kk][tm];
            const float ar[4]={av.x,av.y,av.z,av.w}, cr[4]={cv.x,cv.y,cv.z,cv.w};
            #pragma unroll
            for (int r=0;r<4;r++)
                #pragma unroll
                for (int c=0;c<4;c++)
                    acc[r][c] = fmaf(w, tanh_fast(ar[r]+cr[c]), acc[r][c]);
        }
        if (t+1 < T) {
            const int nxt = cur ^ 1;
            P1s[nxt][ad+0][ai]=rA.x; P1s[nxt][ad+1][ai]=rA.y;
            P1s[nxt][ad+2][ai]=rA.z; P1s[nxt][ad+3][ai]=rA.w;
            P2s[nxt][ad+0][ai]=rB.x; P2s[nxt][ad+1][ai]=rB.y;
            P2s[nxt][ad+2][ai]=rB.z; P2s[nxt][ad+3][ai]=rB.w;
            __syncthreads();
        }
    }
    float mrow[4], mcol[4];
    #pragma unroll
    for (int r=0;r<4;r++) mrow[r] = (1.0f - m1[(l0+ti+r)*BB + b]) * NEGC;
    #pragma unroll
    for (int c=0;c<4;c++) mcol[c] = (1.0f - m2[(m0+tm+c)*BB + b]) * NEGC;
    #pragma unroll
    for (int r=0;r<4;r++)
        #pragma unroll
        for (int c=0;c<4;c++)
            acc[r][c] += mrow[r] + mcol[c];
    #pragma unroll
    for (int r=0;r<4;r++)
        *(float4*)&g_aff[((size_t)(b*L1N)+(l0+ti+r))*L2N + m0 + tm]
            = make_float4(acc[r][0],acc[r][1],acc[r][2],acc[r][3]);
    #pragma unroll
    for (int c=0;c<4;c++)
        *(float4*)&g_afft[((size_t)(b*L2N)+(m0+tm+c))*L1N + l0 + ti]
            = make_float4(acc[0][c],acc[1][c],acc[2][c],acc[3][c]);
}

// =====================================================================
// Dual row softmax: grid (B*512, 2)
// =====================================================================
__global__ __launch_bounds__(128) void softmax_dual_kernel()
{
    const int row = blockIdx.x;
    const float* src = blockIdx.y ? g_afft : g_aff;
    float*       dst = blockIdx.y ? g_d21t : g_d12;
    const float4 v = ((const float4*)&src[(size_t)row*512])[threadIdx.x];
    float mx = fmaxf(fmaxf(v.x,v.y), fmaxf(v.z,v.w));
    #pragma unroll
    for (int o=16;o;o>>=1) mx = fmaxf(mx, __shfl_xor_sync(0xffffffffu, mx, o));
    __shared__ float redm[4], reds[4];
    const int wid = threadIdx.x >> 5, lane = threadIdx.x & 31;
    if (!lane) redm[wid] = mx;
    __syncthreads();
    mx = fmaxf(fmaxf(redm[0],redm[1]), fmaxf(redm[2],redm[3]));
    float e0=__expf(v.x-mx), e1=__expf(v.y-mx), e2=__expf(v.z-mx), e3=__expf(v.w-mx);
    float s = (e0+e1)+(e2+e3);
    #pragma unroll
    for (int o=16;o;o>>=1) s += __shfl_xor_sync(0xffffffffu, s, o);
    if (!lane) reds[wid] = s;
    __syncthreads();
    s = (reds[0]+reds[1])+(reds[2]+reds[3]);
    const float inv = 1.0f / s;
    ((float4*)&dst[(size_t)row*512])[threadIdx.x]
        = make_float4(e0*inv, e1*inv, e2*inv, e3*inv);
}

// =====================================================================
// Context GEMMs, K-split 2x:
//  which=0: c12[b,m,d] = sum_l d12 [b,l,m] * ctx1[l,b,d]
//  which=1: c21[b,l,d] = sum_m d21t[b,m,l] * ctx2[m,b,d]
// grid (4, 8, 8): x=j0, y=i0, z = which*4 + b*2 + ks. 256 threads.
// =====================================================================
__global__ __launch_bounds__(256) void context_kernel(
    const float* __restrict__ ctx1, const float* __restrict__ ctx2)
{
    const int which = blockIdx.z >> 2;
    const int b     = (blockIdx.z >> 1) & 1;
    const int ks    = blockIdx.z & 1;
    const float* Asrc = which ? g_d21t : g_d12;
    const float* Bsrc = which ? ctx2   : ctx1;
    float*       Cdst = which ? g_c21h[ks] : g_c12h[ks];
    const int i0 = blockIdx.y * 64;
    const int j0 = blockIdx.x * 64;
    const int k00 = ks * 256;
    const int tid = threadIdx.x;
    __shared__ __align__(16) float As[2][16][68];
    __shared__ __align__(16) float Bs[2][16][64];
    u64 acc[4][2] = {};
    const int ak = tid >> 4, am = (tid & 15) << 2;
    const int bk = tid >> 4, bj = (tid & 15) << 2;
    const int ti = (tid >> 4) << 2, tj = (tid & 15) << 2;

    float4 rA = *(const float4*)&Asrc[((size_t)(b*L1N)+(k00+ak))*L2N + i0 + am];
    float4 rB = *(const float4*)&Bsrc[((size_t)(k00+bk)*BB + b)*D1N + j0 + bj];
    *(float4*)&As[0][ak][am] = rA;
    *(float4*)&Bs[0][bk][bj] = rB;
    __syncthreads();

    const int T = 256/16;
    #pragma unroll 1
    for (int t = 0; t < T; ++t) {
        const int cur = t & 1;
        if (t+1 < T) {
            const int kn = k00 + (t+1)*16;
            rA = *(const float4*)&Asrc[((size_t)(b*L1N)+(kn+ak))*L2N + i0 + am];
            rB = *(const float4*)&Bsrc[((size_t)(kn+bk)*BB + b)*D1N + j0 + bj];
        }
        #pragma unroll
        for (int k = 0; k < 16; ++k) FMA2_STEP(As[cur], Bs[cur], k);
        if (t+1 < T) {
            const int nxt = cur ^ 1;
            *(float4*)&As[nxt][ak][am] = rA;
            *(float4*)&Bs[nxt][bk][bj] = rB;
            __syncthreads();
        }
    }
    #pragma unroll
    for (int r=0;r<4;r++){
        float2 lo = unpack2(acc[r][0]), hi = unpack2(acc[r][1]);
        *(float4*)&Cdst[((size_t)(b*L1N)+(i0+ti+r))*D1N + j0 + tj]
            = make_float4(lo.x,lo.y,hi.x,hi.y);
    }
}

// =====================================================================
// Output GEMMs + tanh epilogue + scatter. A = sum of context halves.
//  which=0: seq_2_to_1 = tanh(q1 + (c21a+c21b) @ W21[D1:] + b21)
//  which=1: seq_1_to_2 = tanh(q2 + (c12a+c12b) @ W12[D2:] + b12)
// grid (4, 16, 2), 256 threads
// =====================================================================
__global__ __launch_bounds__(256) void out_kernel(
    const float* __restrict__ W12, const float* __restrict__ b12,
    const float* __restrict__ W21, const float* __restrict__ b21,
    float* __restrict__ out)
{
    const int which = blockIdx.z;
    const float* A0   = which ? g_c12h[0] : g_c21h[0];
    const float* A1   = which ? g_c12h[1] : g_c21h[1];
    const float* Bm   = which ? (W12 + (size_t)D2N*BNN) : (W21 + (size_t)D1N*BNN);
    const float* bias = which ? b12 : b21;
    const float* Q    = which ? g_q2 : g_q1;
    float* O          = out + (which ? (size_t)L1N*BB*BNN : 0);
    const int i0 = blockIdx.y * 64;
    const int j0 = blockIdx.x * 64;
    const int tid = threadIdx.x;
    __shared__ __align__(16) float As[2][16][68];
    __shared__ __align__(16) float Bs[2][16][64];
    u64 acc[4][2] = {};
    const int ai = tid >> 2, ad = (tid & 3) << 2;
    const int bk = tid >> 4, bj = (tid & 15) << 2;
    const int ti = (tid >> 4) << 2, tj = (tid & 15) << 2;

    const size_t arow = (size_t)(i0+ai)*D1N + ad;
    float4 rA = f4add(*(const float4*)&A0[arow], *(const float4*)&A1[arow]);
    float4 rB = *(const float4*)&Bm[(size_t)bk*BNN + j0 + bj];
    As[0][ad+0][ai]=rA.x; As[0][ad+1][ai]=rA.y; As[0][ad+2][ai]=rA.z; As[0][ad+3][ai]=rA.w;
    *(float4*)&Bs[0][bk][bj] = rB;
    __syncthreads();

    const int T = D1N/16;
    #pragma unroll 1
    for (int t = 0; t < T; ++t) {
        const int cur = t & 1;
        if (t+1 < T) {
            rA = f4add(*(const float4*)&A0[arow + (t+1)*16],
                       *(const float4*)&A1[arow + (t+1)*16]);
            rB = *(const float4*)&Bm[(size_t)((t+1)*16+bk)*BNN + j0 + bj];
        }
        #pragma unroll
        for (int k = 0; k < 16; ++k) FMA2_STEP(As[cur], Bs[cur], k);
        if (t+1 < T) {
            const int nxt = cur ^ 1;
            As[nxt][ad+0][ai]=rA.x; As[nxt][ad+1][ai]=rA.y;
            As[nxt][ad+2][ai]=rA.z; As[nxt][ad+3][ai]=rA.w;
            *(float4*)&Bs[nxt][bk][bj] = rB;
            __syncthreads();
        }
    }
    const float4 bb = *(const float4*)&bias[j0+tj];
    #pragma unroll
    for (int r=0;r<4;r++){
        const int row = i0+ti+r;              // row = b*512 + seqpos
        const int b = row >> 9, sp = row & 511;
        const float4 q = *(const float4*)&Q[(size_t)row*BNN + j0 + tj];
        float2 lo = unpack2(acc[r][0]), hi = unpack2(acc[r][1]);
        float4 o;
        o.x = tanhf(lo.x+q.x+bb.x);
        o.y = tanhf(lo.y+q.y+bb.y);
        o.z = tanhf(hi.x+q.z+bb.z);
        o.w = tanhf(hi.y+q.w+bb.w);
        *(float4*)&O[((size_t)(sp*BB)+b)*BNN + j0 + tj] = o;
    }
}

// =====================================================================
extern "C" void kernel_launch(void* const* d_in, const int* in_sizes, int n_in,
                              void* d_out, int out_size)
{
    (void)in_sizes; (void)n_in; (void)out_size;
    const float* ctx1 = (const float*)d_in[0];
    const float* ctx2 = (const float*)d_in[1];
    const float* m1   = (const float*)d_in[2];
    const float* m2   = (const float*)d_in[3];
    const float* Wh   = (const float*)d_in[4];
    const float* bh   = (const float*)d_in[5];
    const float* wo   = (const float*)d_in[6];
    const float* W12  = (const float*)d_in[7];
    const float* b12  = (const float*)d_in[8];
    const float* W21  = (const float*)d_in[9];
    const float* b21  = (const float*)d_in[10];
    float* out = (float*)d_out;

    proj_p_kernel      <<<dim3(4, 8, 8),  256>>>(ctx1, ctx2, Wh, bh);
    affinity_q_kernel  <<<dim3(8, 8, 4),  256>>>(ctx1, ctx2, m1, m2, wo, W12, W21);
    softmax_dual_kernel<<<dim3(BB*L1N, 2), 128>>>();
    context_kernel     <<<dim3(4, 8, 8),  256>>>(ctx1, ctx2);
    out_kernel         <<<dim3(4, 16, 2), 256>>>(W12, b12, W21, b21, out);
}